// round 15
// baseline (speedup 1.0000x reference)
#include <cuda_runtime.h>
#include <cuda_fp16.h>
#include <math.h>
#include <stdint.h>

#define NMAX  50000
#define EMAX  800000
#define NGR   128

#define TB_BINS  3072          // bins over [0, 1.5), step 1/2048
#define TB_ROWS  (TB_BINS + 1)
#define TB_SCALE 2048.0f
#define TB_DMAX  1.49951f

#define SCAN_B 256

// ---------------- scratch (static device arrays: no allocations) ----------------
__device__ __half2 g_actA[(size_t)NMAX * 64];
__device__ __half2 g_actB[(size_t)NMAX * 64];
__device__ float   g_pool[NGR * 32];

// CSR by dst + packed edge records (CSR order), 32B each:
// u0 = { srcn, bin|xs<<16, h2(sh0,sh1), h2(sh2,sh3) }
// u1 = { h2(sh4,sh5), h2(sh6,sh7), h2(sh8,0), 0 }
__device__ int      g_cnt[NMAX];
__device__ int      g_off[NMAX];
__device__ int      g_pos[NMAX];
__device__ unsigned g_erec[(size_t)EMAX * 8];
__device__ int      g_bsum[(NMAX + SCAN_B - 1) / SCAN_B + 1];

// radial-weight tables (cutoff folded in), fp16
__device__ __half2 g_tab1h[(size_t)TB_ROWS * 32];   // [row][lane] = {p0,p1}
__device__ uint2   g_tab2a[(size_t)TB_ROWS * 32];   // [row][lane] = {h2(p0,p1), h2(p2,p3)}
__device__ __half2 g_tab2b[(size_t)TB_ROWS * 32];   // [row][lane] = {p4,p5}
__device__ __half2 g_tab3h[(size_t)TB_ROWS * 32];   // [row][lane] = {p0,p1}

// ---------------- helpers ----------------
__device__ __forceinline__ float sspf(float x) {
    return fmaxf(x, 0.f) + log1pf(__expf(-fabsf(x))) - 0.69314718055994530942f;
}
__device__ __forceinline__ float cutoff_w(float d) {
    float u = d * (1.0f / 1.5f);
    if (u >= 1.f) return 0.f;
    float u2v = u * u;
    float u6 = u2v * u2v * u2v;
    return 1.f + u6 * (-28.f + u * (48.f - 21.f * u));
}
__device__ __forceinline__ float2 h2f(unsigned bits) {
    __half2 h = *reinterpret_cast<__half2*>(&bits);
    return __half22float2(h);
}

// ---------------- table generation (emb/cutoff inline) ----------------
// per_row = 32(t1) + 32(t2a: paths 0-3) + 32(t2b: paths 4-5) + 32(t3) = 128
__global__ void k_tab_build_all(
    const float* __restrict__ W1, const float* __restrict__ b1,
    const float* __restrict__ W2, const float* __restrict__ b2,
    const float* __restrict__ W3, const float* __restrict__ b3)
{
    int t = blockIdx.x * blockDim.x + threadIdx.x;
    if (t >= TB_ROWS * 128) return;
    int r = t >> 7, rem = t & 127;
    int sec = rem >> 5, lane = rem & 31;

    float d = (float)r * (1.0f / TB_SCALE);
    float ew = cutoff_w(d);
    float emb[10];
    #pragma unroll
    for (int k = 0; k < 10; k++) {
        float mu = 0.7f + (float)k * 0.111111111111111111f;
        float dd = d - mu;
        emb[k] = __expf(-50.f * dd * dd);
    }

    if (sec == 1) {   // tab2a: 4 columns (paths 0..3)
        float v[4];
        #pragma unroll
        for (int p = 0; p < 4; p++) v[p] = b2[p * 32 + lane];
        #pragma unroll
        for (int k = 0; k < 10; k++) {
            #pragma unroll
            for (int p = 0; p < 4; p++)
                v[p] = fmaf(emb[k], W2[k * 192 + p * 32 + lane], v[p]);
        }
        __half2 h01 = __floats2half2_rn(v[0] * ew, v[1] * ew);
        __half2 h23 = __floats2half2_rn(v[2] * ew, v[3] * ew);
        g_tab2a[r * 32 + lane] = make_uint2(*reinterpret_cast<unsigned*>(&h01),
                                            *reinterpret_cast<unsigned*>(&h23));
        return;
    }

    const float* W; const float* b; __half2* out; int C; int pofs;
    if (sec == 0)      { W = W2; b = b2; C = 192; pofs = 4; out = g_tab2b; }   // paths 4,5
    else if (sec == 2) { W = W1; b = b1; C = 64;  pofs = 0; out = g_tab1h; }
    else               { W = W3; b = b3; C = 64;  pofs = 0; out = g_tab3h; }

    int c0 = pofs * 32 + lane;
    int c1 = (pofs + 1) * 32 + lane;
    float v0 = b[c0], v1 = b[c1];
    #pragma unroll
    for (int k = 0; k < 10; k++) {
        v0 = fmaf(emb[k], W[k * C + c0], v0);
        v1 = fmaf(emb[k], W[k * C + c1], v1);
    }
    out[r * 32 + lane] = __floats2half2_rn(v0 * ew, v1 * ew);
}

// ---------------- CSR build ----------------
__global__ void k_hist(const int* __restrict__ ei, int E)
{
    int e = blockIdx.x * blockDim.x + threadIdx.x;
    if (e < NGR * 32) g_pool[e] = 0.f;          // fold pool zeroing in here
    if (e < E) atomicAdd(&g_cnt[ei[E + e]], 1);
}

// scan1: per-block exclusive scan of g_cnt -> g_off (block-local), block total -> g_bsum
__global__ void k_scan1(int n)
{
    __shared__ int sh[SCAN_B];
    int gid = blockIdx.x * SCAN_B + threadIdx.x;
    int v = (gid < n) ? g_cnt[gid] : 0;
    sh[threadIdx.x] = v;
    __syncthreads();
    #pragma unroll
    for (int ofs = 1; ofs < SCAN_B; ofs <<= 1) {
        int t = (threadIdx.x >= ofs) ? sh[threadIdx.x - ofs] : 0;
        __syncthreads();
        sh[threadIdx.x] += t;
        __syncthreads();
    }
    if (gid < n) g_off[gid] = sh[threadIdx.x] - v;
    if (threadIdx.x == SCAN_B - 1) g_bsum[blockIdx.x] = sh[SCAN_B - 1];
}

// scan23: each block reduces preceding block sums itself, applies offset
__global__ void k_scan23(int n)
{
    __shared__ int warp_part[8];
    int nb = blockIdx.x;
    int acc = 0;
    for (int i = threadIdx.x; i < nb; i += SCAN_B) acc += g_bsum[i];
    #pragma unroll
    for (int o = 16; o > 0; o >>= 1) acc += __shfl_down_sync(0xffffffffu, acc, o);
    if ((threadIdx.x & 31) == 0) warp_part[threadIdx.x >> 5] = acc;
    __syncthreads();
    if (threadIdx.x == 0) {
        int s = 0;
        #pragma unroll
        for (int w = 0; w < 8; w++) s += warp_part[w];
        warp_part[0] = s;
    }
    __syncthreads();
    int blockOfs = warp_part[0];
    int gid = blockIdx.x * SCAN_B + threadIdx.x;
    if (gid < n) {
        int o = g_off[gid] + blockOfs;
        g_off[gid] = o;
        g_pos[gid] = o;
    }
}

// scatter + build packed 32B record at CSR slot
__global__ void k_scatter(const int* __restrict__ ei, const float* __restrict__ elen,
                          const float* __restrict__ esh, const float* __restrict__ x, int E)
{
    int e = blockIdx.x * blockDim.x + threadIdx.x;
    if (e >= E) return;
    int d = ei[E + e];
    int p = atomicAdd(&g_pos[d], 1);
    int s = ei[e];
    float dd = elen[e];
    float tt = fminf(fmaxf(dd, 0.f), TB_DMAX) * TB_SCALE;
    unsigned bin = (unsigned)(int)(tt + 0.5f);
    const float* sh = esh + (size_t)e * 9;

    __half xsh = __float2half_rn(x[s]);
    unsigned w1 = bin | ((unsigned)__half_as_ushort(xsh) << 16);
    __half2 p01 = __floats2half2_rn(sh[0], sh[1]);
    __half2 p23 = __floats2half2_rn(sh[2], sh[3]);
    __half2 p45 = __floats2half2_rn(sh[4], sh[5]);
    __half2 p67 = __floats2half2_rn(sh[6], sh[7]);
    __half2 p8z = __floats2half2_rn(sh[8], 0.f);

    uint4 u0 = make_uint4((unsigned)s, w1,
                          *reinterpret_cast<unsigned*>(&p01),
                          *reinterpret_cast<unsigned*>(&p23));
    uint4 u1 = make_uint4(*reinterpret_cast<unsigned*>(&p45),
                          *reinterpret_cast<unsigned*>(&p67),
                          *reinterpret_cast<unsigned*>(&p8z), 0u);
    uint4* out = (uint4*)(g_erec + (size_t)p * 8);
    out[0] = u0; out[1] = u1;
}

// ---------------- feature fetch / write ----------------
__device__ __forceinline__ void gather_feat(const __half2* base, int node, int lane,
                                            float& x0, float& xv0, float& xv1, float& xv2)
{
    const uint2* p = (const uint2*)(base + (size_t)node * 64 + lane * 2);
    uint2 raw = __ldg(p);
    float2 f01 = h2f(raw.x);
    float2 f23 = h2f(raw.y);
    x0 = f01.x; xv0 = f01.y; xv1 = f23.x; xv2 = f23.y;
}

__device__ __forceinline__ void write_normact(__half2* base, int node, int lane,
                                              float s, float v0, float v1, float v2)
{
    float nr = sqrtf(v0 * v0 + v1 * v1 + v2 * v2 + 1e-12f);
    float sc = sspf(nr) / nr;
    uint2 o;
    __half2 h01 = __floats2half2_rn(sspf(s), v0 * sc);
    __half2 h23 = __floats2half2_rn(v1 * sc, v2 * sc);
    o.x = *reinterpret_cast<unsigned*>(&h01);
    o.y = *reinterpret_cast<unsigned*>(&h23);
    *(uint2*)(base + (size_t)node * 64 + lane * 2) = o;
}

// ---------------- layer 1 (dst-major, fused norm-act) ----------------
__global__ void __launch_bounds__(256) k_layer1(int E, int N)
{
    int node = (blockIdx.x * blockDim.x + threadIdx.x) >> 5;
    if (node >= N) return;
    int lane = threadIdx.x & 31;
    int beg = __ldg(&g_off[node]);
    int end = (node + 1 < N) ? __ldg(&g_off[node + 1]) : E;

    float a0 = 0.f, a1 = 0.f, a2 = 0.f, a3 = 0.f;
    #pragma unroll 4
    for (int i = beg; i < end; i++) {
        uint4 u0 = __ldg((const uint4*)(g_erec + (size_t)i * 8));
        int bin = (int)(u0.y & 0xFFFFu);
        float xs = __half2float(__ushort_as_half((unsigned short)(u0.y >> 16)));
        float2 s01 = h2f(u0.z);
        float2 s23 = h2f(u0.w);
        float2 wv = __half22float2(__ldg(g_tab1h + (size_t)bin * 32 + lane));
        float xw0 = xs * wv.x;
        float xw1 = xs * wv.y;
        a0 += xw0 * s01.x;
        a1 += xw1 * s01.y;
        a2 += xw1 * s23.x;
        a3 += xw1 * s23.y;
    }
    write_normact(g_actA, node, lane, a0, a1, a2, a3);
}

// ---------------- layer 2 (dst-major, fused norm-act) ----------------
__global__ void __launch_bounds__(256) k_layer2(int E, int N)
{
    int node = (blockIdx.x * blockDim.x + threadIdx.x) >> 5;
    if (node >= N) return;
    int lane = threadIdx.x & 31;
    int beg = __ldg(&g_off[node]);
    int end = (node + 1 < N) ? __ldg(&g_off[node + 1]) : E;

    const float RT3I = 0.57735026918962576451f;  // 1/sqrt(3)
    const float RT2I = 0.70710678118654752440f;  // 1/sqrt(2)
    const float A    = 0.31622776601683793320f;  // 1/sqrt(10)
    const float B    = 0.54772255750516611346f;  // sqrt(3/10)

    float a0 = 0.f, a1 = 0.f, a2 = 0.f, a3 = 0.f;
    #pragma unroll 2
    for (int i = beg; i < end; i++) {
        const uint4* rp = (const uint4*)(g_erec + (size_t)i * 8);
        uint4 u0 = __ldg(rp);
        uint4 u1 = __ldg(rp + 1);
        int srcn = (int)u0.x;
        int bin  = (int)(u0.y & 0xFFFFu);

        float x0, xv0, xv1, xv2;
        gather_feat(g_actA, srcn, lane, x0, xv0, xv1, xv2);

        uint2 wpair = __ldg(g_tab2a + (size_t)bin * 32 + lane);
        float2 w01 = h2f(wpair.x);
        float2 w23 = h2f(wpair.y);
        float2 w45 = __half22float2(__ldg(g_tab2b + (size_t)bin * 32 + lane));

        float2 s01 = h2f(u0.z);
        float2 s23 = h2f(u0.w);
        float2 s45 = h2f(u1.x);
        float2 s67 = h2f(u1.y);
        float2 s8z = h2f(u1.z);
        float s0  = s01.x;
        float sv0 = s01.y, sv1 = s23.x, sv2 = s23.y;
        float t20 = s45.x, t21 = s45.y, t22 = s67.x, t23 = s67.y, t24 = s8z.x;

        // paths (0,0,0) + (1,1,0)
        float dotv = xv0 * sv0 + xv1 * sv1 + xv2 * sv2;
        float m0 = s0 * x0 * w01.x - RT3I * dotv * w23.y;

        // path (1,1,1): -1/sqrt2 * cross
        float cr0 = xv1 * sv2 - xv2 * sv1;
        float cr1 = xv2 * sv0 - xv0 * sv2;
        float cr2 = xv0 * sv1 - xv1 * sv0;

        // path (1,2,1): real CG(1,2,1) contraction
        float t50 =  A * xv0 * t22 + B * xv0 * t24 - B * xv1 * t21 - B * xv2 * t20;
        float t51 = -B * xv0 * t21 - 2.f * A * xv1 * t22 - B * xv2 * t23;
        float t52 = -B * xv0 * t20 - B * xv1 * t23 + A * xv2 * t22 - B * xv2 * t24;

        float x0w1 = x0 * w01.y;
        float s0w2 = s0 * w23.x;
        float wn4  = -RT2I * w45.x;
        a0 += m0;
        a1 += sv0 * x0w1 + xv0 * s0w2 + cr0 * wn4 + t50 * w45.y;
        a2 += sv1 * x0w1 + xv1 * s0w2 + cr1 * wn4 + t51 * w45.y;
        a3 += sv2 * x0w1 + xv2 * s0w2 + cr2 * wn4 + t52 * w45.y;
    }
    write_normact(g_actB, node, lane, a0, a1, a2, a3);
}

// ---------------- layer 3 (dst-major) + silu + pool ----------------
__global__ void __launch_bounds__(256) k_layer3(const int* __restrict__ batch, int E, int N)
{
    int node = (blockIdx.x * blockDim.x + threadIdx.x) >> 5;
    if (node >= N) return;
    int lane = threadIdx.x & 31;
    int beg = __ldg(&g_off[node]);
    int end = (node + 1 < N) ? __ldg(&g_off[node + 1]) : E;

    const float RT3I = 0.57735026918962576451f;
    float h = 0.f;
    #pragma unroll 4
    for (int i = beg; i < end; i++) {
        uint4 u0 = __ldg((const uint4*)(g_erec + (size_t)i * 8));
        int srcn = (int)u0.x;
        int bin  = (int)(u0.y & 0xFFFFu);

        float x0, xv0, xv1, xv2;
        gather_feat(g_actB, srcn, lane, x0, xv0, xv1, xv2);
        float2 wv = __half22float2(__ldg(g_tab3h + (size_t)bin * 32 + lane));

        float2 s01 = h2f(u0.z);
        float2 s23 = h2f(u0.w);
        float dotv = xv0 * s01.y + xv1 * s23.x + xv2 * s23.y;
        h += x0 * s01.x * wv.x - RT3I * dotv * wv.y;
    }
    float y = h / (1.f + __expf(-h));   // silu
    atomicAdd(&g_pool[__ldg(&batch[node]) * 32 + lane], y);
}

// ---------------- head ----------------
__global__ void k_head(const float* __restrict__ Wo, const float* __restrict__ bo,
                       float* __restrict__ out)
{
    __shared__ float Ws[32 * 8];
    __shared__ float bs[8];
    int t = threadIdx.x;
    if (t < 256) Ws[t] = Wo[t];
    if (t < 8)   bs[t] = bo[t];
    __syncthreads();
    if (t < NGR) {
        float acc[8];
        #pragma unroll
        for (int j = 0; j < 8; j++) acc[j] = bs[j];
        #pragma unroll
        for (int k = 0; k < 32; k++) {
            float gv = g_pool[t * 32 + k];
            #pragma unroll
            for (int j = 0; j < 8; j++) acc[j] = fmaf(gv, Ws[k * 8 + j], acc[j]);
        }
        float mx = acc[0];
        #pragma unroll
        for (int j = 1; j < 8; j++) mx = fmaxf(mx, acc[j]);
        float sm = 0.f;
        #pragma unroll
        for (int j = 0; j < 8; j++) { acc[j] = __expf(acc[j] - mx); sm += acc[j]; }
        float inv = 1.f / sm;
        #pragma unroll
        for (int j = 0; j < 8; j++) out[t * 8 + j] = acc[j] * inv;
    }
}

// ---------------- host ----------------
extern "C" void kernel_launch(void* const* d_in, const int* in_sizes, int n_in,
                              void* d_out, int out_size)
{
    int ix, ish, ilen, iW1, ib1, iW2, ib2, iW3, ib3, iWo, ibo, iei, ibatch;
    if (n_in >= 13 && (long long)in_sizes[1] == 9LL * (long long)in_sizes[2]) {
        ix = 0; ish = 1; ilen = 2; iW1 = 3; ib1 = 4; iW2 = 5; ib2 = 6;
        iW3 = 7; ib3 = 8; iWo = 9; ibo = 10; iei = 11; ibatch = 12;
    } else {
        ix = 0; iei = 1; ish = 2; ilen = 3; ibatch = 4; iW1 = 5; ib1 = 6;
        iW2 = 7; ib2 = 8; iW3 = 9; ib3 = 10; iWo = 11; ibo = 12;
    }

    const float* x     = (const float*)d_in[ix];
    const float* esh   = (const float*)d_in[ish];
    const float* elen  = (const float*)d_in[ilen];
    const float* W1    = (const float*)d_in[iW1];
    const float* b1    = (const float*)d_in[ib1];
    const float* W2    = (const float*)d_in[iW2];
    const float* b2    = (const float*)d_in[ib2];
    const float* W3    = (const float*)d_in[iW3];
    const float* b3    = (const float*)d_in[ib3];
    const float* Wo    = (const float*)d_in[iWo];
    const float* bo    = (const float*)d_in[ibo];
    const int*   ei    = (const int*)d_in[iei];
    const int*   batch = (const int*)d_in[ibatch];

    int N = in_sizes[ix];
    int E = in_sizes[ilen];
    if (N > NMAX) N = NMAX;
    if (E > EMAX) E = EMAX;

    void* pcnt;
    cudaGetSymbolAddress(&pcnt, g_cnt);

    int nbE = (E + 255) / 256;
    int nbS = (N + SCAN_B - 1) / SCAN_B;
    int nbW = (N * 32 + 255) / 256;

    // Radial-weight tables (emb/cutoff inline, cutoff folded in)
    k_tab_build_all<<<(TB_ROWS * 128 + 255) / 256, 256>>>(W1, b1, W2, b2, W3, b3);

    // CSR by dst + packed records
    cudaMemsetAsync(pcnt, 0, (size_t)N * sizeof(int), 0);
    k_hist<<<nbE, 256>>>(ei, E);            // also zeroes g_pool
    k_scan1<<<nbS, SCAN_B>>>(N);
    k_scan23<<<nbS, SCAN_B>>>(N);
    k_scatter<<<nbE, 256>>>(ei, elen, esh, x, E);

    // Layers (dst-major, fused norm-act)
    k_layer1<<<nbW, 256>>>(E, N);
    k_layer2<<<nbW, 256>>>(E, N);
    k_layer3<<<nbW, 256>>>(batch, E, N);
    k_head<<<1, 256>>>(Wo, bo, (float*)d_out);
}

// round 16
// speedup vs baseline: 1.0538x; 1.0538x over previous
#include <cuda_runtime.h>
#include <cuda_fp16.h>
#include <math.h>
#include <stdint.h>

#define NMAX  50000
#define EMAX  800000
#define NGR   128

#define TB_BINS  3072          // bins over [0, 1.5), step 1/2048
#define TB_ROWS  (TB_BINS + 1)
#define TB_SCALE 2048.0f
#define TB_DMAX  1.49951f

#define SCAN_B 256

// ---------------- scratch (static device arrays: no allocations) ----------------
__device__ __half2 g_actA[(size_t)NMAX * 64];
__device__ __half2 g_actB[(size_t)NMAX * 64];
__device__ float   g_pool[NGR * 32];

// CSR by dst + packed edge records (CSR order), 32B each:
// u0 = { srcn, bin|xs<<16, h2(sh0,sh1), h2(sh2,sh3) }
// u1 = { h2(sh4,sh5), h2(sh6,sh7), h2(sh8,0), 0 }
__device__ int      g_cnt[NMAX];
__device__ int      g_off[NMAX];
__device__ int      g_pos[NMAX];
__device__ unsigned g_erec[(size_t)EMAX * 8];
__device__ int      g_bsum[(NMAX + SCAN_B - 1) / SCAN_B + 1];

// radial-weight tables (cutoff folded in), fp16 path-paired
__device__ __half2 g_tab1h[(size_t)TB_ROWS * 32];
__device__ __half2 g_tab2h[(size_t)TB_ROWS * 96];
__device__ __half2 g_tab3h[(size_t)TB_ROWS * 32];

// ---------------- helpers ----------------
__device__ __forceinline__ float sspf(float x) {
    return fmaxf(x, 0.f) + log1pf(__expf(-fabsf(x))) - 0.69314718055994530942f;
}
__device__ __forceinline__ float cutoff_w(float d) {
    float u = d * (1.0f / 1.5f);
    if (u >= 1.f) return 0.f;
    float u2v = u * u;
    float u6 = u2v * u2v * u2v;
    return 1.f + u6 * (-28.f + u * (48.f - 21.f * u));
}
__device__ __forceinline__ float2 h2f(unsigned bits) {
    __half2 h = *reinterpret_cast<__half2*>(&bits);
    return __half22float2(h);
}

// ---------------- table generation (emb/cutoff inline) + g_cnt zeroing ----------------
// per_row = 32(t1) + 96(t2) + 32(t3) = 160
__global__ void k_tab_build_all(
    const float* __restrict__ W1, const float* __restrict__ b1,
    const float* __restrict__ W2, const float* __restrict__ b2,
    const float* __restrict__ W3, const float* __restrict__ b3)
{
    int t = blockIdx.x * blockDim.x + threadIdx.x;
    if (t < NMAX) g_cnt[t] = 0;                 // fold g_cnt zeroing in here
    if (t >= TB_ROWS * 160) return;
    int r = t / 160, rem = t - r * 160;

    float d = (float)r * (1.0f / TB_SCALE);
    float ew = cutoff_w(d);
    float emb[10];
    #pragma unroll
    for (int k = 0; k < 10; k++) {
        float mu = 0.7f + (float)k * 0.111111111111111111f;
        float dd = d - mu;
        emb[k] = __expf(-50.f * dd * dd);
    }

    const float* W; const float* b; __half2* out; int C; int pp; int lane; int oidx;
    if (rem < 32)       { W = W1; b = b1; C = 64;  pp = 0;               lane = rem;      out = g_tab1h; oidx = r * 32 + rem; }
    else if (rem < 128) { W = W2; b = b2; C = 192; pp = (rem - 32) >> 5; lane = rem & 31; out = g_tab2h; oidx = r * 96 + (rem - 32); }
    else                { W = W3; b = b3; C = 64;  pp = 0;               lane = rem & 31; out = g_tab3h; oidx = r * 32 + (rem - 128); }

    int c0 = (2 * pp) * 32 + lane;
    int c1 = (2 * pp + 1) * 32 + lane;
    float v0 = b[c0], v1 = b[c1];
    #pragma unroll
    for (int k = 0; k < 10; k++) {
        v0 = fmaf(emb[k], W[k * C + c0], v0);
        v1 = fmaf(emb[k], W[k * C + c1], v1);
    }
    out[oidx] = __floats2half2_rn(v0 * ew, v1 * ew);
}

// ---------------- CSR build ----------------
__global__ void k_hist(const int* __restrict__ ei, int E)
{
    int e = blockIdx.x * blockDim.x + threadIdx.x;
    if (e < NGR * 32) g_pool[e] = 0.f;          // fold pool zeroing in here
    if (e < E) atomicAdd(&g_cnt[ei[E + e]], 1);
}

// scan1: per-block exclusive scan of g_cnt -> g_off (block-local), block total -> g_bsum
__global__ void k_scan1(int n)
{
    __shared__ int sh[SCAN_B];
    int gid = blockIdx.x * SCAN_B + threadIdx.x;
    int v = (gid < n) ? g_cnt[gid] : 0;
    sh[threadIdx.x] = v;
    __syncthreads();
    #pragma unroll
    for (int ofs = 1; ofs < SCAN_B; ofs <<= 1) {
        int t = (threadIdx.x >= ofs) ? sh[threadIdx.x - ofs] : 0;
        __syncthreads();
        sh[threadIdx.x] += t;
        __syncthreads();
    }
    if (gid < n) g_off[gid] = sh[threadIdx.x] - v;
    if (threadIdx.x == SCAN_B - 1) g_bsum[blockIdx.x] = sh[SCAN_B - 1];
}

// scan23: each block reduces preceding block sums itself, applies offset
__global__ void k_scan23(int n)
{
    __shared__ int warp_part[8];
    int nb = blockIdx.x;
    int acc = 0;
    for (int i = threadIdx.x; i < nb; i += SCAN_B) acc += g_bsum[i];
    #pragma unroll
    for (int o = 16; o > 0; o >>= 1) acc += __shfl_down_sync(0xffffffffu, acc, o);
    if ((threadIdx.x & 31) == 0) warp_part[threadIdx.x >> 5] = acc;
    __syncthreads();
    if (threadIdx.x == 0) {
        int s = 0;
        #pragma unroll
        for (int w = 0; w < 8; w++) s += warp_part[w];
        warp_part[0] = s;
    }
    __syncthreads();
    int blockOfs = warp_part[0];
    int gid = blockIdx.x * SCAN_B + threadIdx.x;
    if (gid < n) {
        int o = g_off[gid] + blockOfs;
        g_off[gid] = o;
        g_pos[gid] = o;
    }
}

// scatter + build packed 32B record at CSR slot
__global__ void k_scatter(const int* __restrict__ ei, const float* __restrict__ elen,
                          const float* __restrict__ esh, const float* __restrict__ x, int E)
{
    int e = blockIdx.x * blockDim.x + threadIdx.x;
    if (e >= E) return;
    int d = ei[E + e];
    int p = atomicAdd(&g_pos[d], 1);
    int s = ei[e];
    float dd = elen[e];
    float tt = fminf(fmaxf(dd, 0.f), TB_DMAX) * TB_SCALE;
    unsigned bin = (unsigned)(int)(tt + 0.5f);
    const float* sh = esh + (size_t)e * 9;

    __half xsh = __float2half_rn(x[s]);
    unsigned w1 = bin | ((unsigned)__half_as_ushort(xsh) << 16);
    __half2 p01 = __floats2half2_rn(sh[0], sh[1]);
    __half2 p23 = __floats2half2_rn(sh[2], sh[3]);
    __half2 p45 = __floats2half2_rn(sh[4], sh[5]);
    __half2 p67 = __floats2half2_rn(sh[6], sh[7]);
    __half2 p8z = __floats2half2_rn(sh[8], 0.f);

    uint4 u0 = make_uint4((unsigned)s, w1,
                          *reinterpret_cast<unsigned*>(&p01),
                          *reinterpret_cast<unsigned*>(&p23));
    uint4 u1 = make_uint4(*reinterpret_cast<unsigned*>(&p45),
                          *reinterpret_cast<unsigned*>(&p67),
                          *reinterpret_cast<unsigned*>(&p8z), 0u);
    uint4* out = (uint4*)(g_erec + (size_t)p * 8);
    out[0] = u0; out[1] = u1;
}

// ---------------- feature fetch / write ----------------
__device__ __forceinline__ void gather_feat(const __half2* base, int node, int lane,
                                            float& x0, float& xv0, float& xv1, float& xv2)
{
    const uint2* p = (const uint2*)(base + (size_t)node * 64 + lane * 2);
    uint2 raw = __ldg(p);
    float2 f01 = h2f(raw.x);
    float2 f23 = h2f(raw.y);
    x0 = f01.x; xv0 = f01.y; xv1 = f23.x; xv2 = f23.y;
}

__device__ __forceinline__ void write_normact(__half2* base, int node, int lane,
                                              float s, float v0, float v1, float v2)
{
    float nr = sqrtf(v0 * v0 + v1 * v1 + v2 * v2 + 1e-12f);
    float sc = sspf(nr) / nr;
    uint2 o;
    __half2 h01 = __floats2half2_rn(sspf(s), v0 * sc);
    __half2 h23 = __floats2half2_rn(v1 * sc, v2 * sc);
    o.x = *reinterpret_cast<unsigned*>(&h01);
    o.y = *reinterpret_cast<unsigned*>(&h23);
    *(uint2*)(base + (size_t)node * 64 + lane * 2) = o;
}

// ---------------- layer 1 (dst-major, fused norm-act) ----------------
__global__ void __launch_bounds__(256) k_layer1(int E, int N)
{
    int node = (blockIdx.x * blockDim.x + threadIdx.x) >> 5;
    if (node >= N) return;
    int lane = threadIdx.x & 31;
    int beg = __ldg(&g_off[node]);
    int end = (node + 1 < N) ? __ldg(&g_off[node + 1]) : E;

    float a0 = 0.f, a1 = 0.f, a2 = 0.f, a3 = 0.f;
    #pragma unroll 2
    for (int i = beg; i < end; i++) {
        uint4 u0 = __ldg((const uint4*)(g_erec + (size_t)i * 8));
        int bin = (int)(u0.y & 0xFFFFu);
        float xs = __half2float(__ushort_as_half((unsigned short)(u0.y >> 16)));
        float2 s01 = h2f(u0.z);
        float2 s23 = h2f(u0.w);
        float2 wv = __half22float2(__ldg(g_tab1h + (size_t)bin * 32 + lane));
        float xw0 = xs * wv.x;
        float xw1 = xs * wv.y;
        a0 += xw0 * s01.x;
        a1 += xw1 * s01.y;
        a2 += xw1 * s23.x;
        a3 += xw1 * s23.y;
    }
    write_normact(g_actA, node, lane, a0, a1, a2, a3);
}

// ---------------- layer 2 (dst-major, fused norm-act) ----------------
__global__ void __launch_bounds__(256) k_layer2(int E, int N)
{
    int node = (blockIdx.x * blockDim.x + threadIdx.x) >> 5;
    if (node >= N) return;
    int lane = threadIdx.x & 31;
    int beg = __ldg(&g_off[node]);
    int end = (node + 1 < N) ? __ldg(&g_off[node + 1]) : E;

    const float RT3I = 0.57735026918962576451f;  // 1/sqrt(3)
    const float RT2I = 0.70710678118654752440f;  // 1/sqrt(2)
    const float A    = 0.31622776601683793320f;  // 1/sqrt(10)
    const float B    = 0.54772255750516611346f;  // sqrt(3/10)

    float a0 = 0.f, a1 = 0.f, a2 = 0.f, a3 = 0.f;
    #pragma unroll 2
    for (int i = beg; i < end; i++) {
        const uint4* rp = (const uint4*)(g_erec + (size_t)i * 8);
        uint4 u0 = __ldg(rp);
        uint4 u1 = __ldg(rp + 1);
        int srcn = (int)u0.x;
        int bin  = (int)(u0.y & 0xFFFFu);

        float x0, xv0, xv1, xv2;
        gather_feat(g_actA, srcn, lane, x0, xv0, xv1, xv2);

        const __half2* tb = g_tab2h + (size_t)bin * 96 + lane;
        float2 w01 = __half22float2(__ldg(tb));
        float2 w23 = __half22float2(__ldg(tb + 32));
        float2 w45 = __half22float2(__ldg(tb + 64));

        float2 s01 = h2f(u0.z);
        float2 s23 = h2f(u0.w);
        float2 s45 = h2f(u1.x);
        float2 s67 = h2f(u1.y);
        float2 s8z = h2f(u1.z);
        float s0  = s01.x;
        float sv0 = s01.y, sv1 = s23.x, sv2 = s23.y;
        float t20 = s45.x, t21 = s45.y, t22 = s67.x, t23 = s67.y, t24 = s8z.x;

        // paths (0,0,0) + (1,1,0)
        float dotv = xv0 * sv0 + xv1 * sv1 + xv2 * sv2;
        float m0 = s0 * x0 * w01.x - RT3I * dotv * w23.y;

        // path (1,1,1): -1/sqrt2 * cross
        float cr0 = xv1 * sv2 - xv2 * sv1;
        float cr1 = xv2 * sv0 - xv0 * sv2;
        float cr2 = xv0 * sv1 - xv1 * sv0;

        // path (1,2,1): real CG(1,2,1) contraction
        float t50 =  A * xv0 * t22 + B * xv0 * t24 - B * xv1 * t21 - B * xv2 * t20;
        float t51 = -B * xv0 * t21 - 2.f * A * xv1 * t22 - B * xv2 * t23;
        float t52 = -B * xv0 * t20 - B * xv1 * t23 + A * xv2 * t22 - B * xv2 * t24;

        float x0w1 = x0 * w01.y;
        float s0w2 = s0 * w23.x;
        float wn4  = -RT2I * w45.x;
        a0 += m0;
        a1 += sv0 * x0w1 + xv0 * s0w2 + cr0 * wn4 + t50 * w45.y;
        a2 += sv1 * x0w1 + xv1 * s0w2 + cr1 * wn4 + t51 * w45.y;
        a3 += sv2 * x0w1 + xv2 * s0w2 + cr2 * wn4 + t52 * w45.y;
    }
    write_normact(g_actB, node, lane, a0, a1, a2, a3);
}

// ---------------- layer 3 (dst-major) + silu + pool ----------------
__global__ void __launch_bounds__(256) k_layer3(const int* __restrict__ batch, int E, int N)
{
    int node = (blockIdx.x * blockDim.x + threadIdx.x) >> 5;
    if (node >= N) return;
    int lane = threadIdx.x & 31;
    int beg = __ldg(&g_off[node]);
    int end = (node + 1 < N) ? __ldg(&g_off[node + 1]) : E;

    const float RT3I = 0.57735026918962576451f;
    float h = 0.f;
    #pragma unroll 2
    for (int i = beg; i < end; i++) {
        uint4 u0 = __ldg((const uint4*)(g_erec + (size_t)i * 8));
        int srcn = (int)u0.x;
        int bin  = (int)(u0.y & 0xFFFFu);

        float x0, xv0, xv1, xv2;
        gather_feat(g_actB, srcn, lane, x0, xv0, xv1, xv2);
        float2 wv = __half22float2(__ldg(g_tab3h + (size_t)bin * 32 + lane));

        float2 s01 = h2f(u0.z);
        float2 s23 = h2f(u0.w);
        float dotv = xv0 * s01.y + xv1 * s23.x + xv2 * s23.y;
        h += x0 * s01.x * wv.x - RT3I * dotv * wv.y;
    }
    float y = h / (1.f + __expf(-h));   // silu
    atomicAdd(&g_pool[__ldg(&batch[node]) * 32 + lane], y);
}

// ---------------- head ----------------
__global__ void k_head(const float* __restrict__ Wo, const float* __restrict__ bo,
                       float* __restrict__ out)
{
    __shared__ float Ws[32 * 8];
    __shared__ float bs[8];
    int t = threadIdx.x;
    if (t < 256) Ws[t] = Wo[t];
    if (t < 8)   bs[t] = bo[t];
    __syncthreads();
    if (t < NGR) {
        float acc[8];
        #pragma unroll
        for (int j = 0; j < 8; j++) acc[j] = bs[j];
        #pragma unroll
        for (int k = 0; k < 32; k++) {
            float gv = g_pool[t * 32 + k];
            #pragma unroll
            for (int j = 0; j < 8; j++) acc[j] = fmaf(gv, Ws[k * 8 + j], acc[j]);
        }
        float mx = acc[0];
        #pragma unroll
        for (int j = 1; j < 8; j++) mx = fmaxf(mx, acc[j]);
        float sm = 0.f;
        #pragma unroll
        for (int j = 0; j < 8; j++) { acc[j] = __expf(acc[j] - mx); sm += acc[j]; }
        float inv = 1.f / sm;
        #pragma unroll
        for (int j = 0; j < 8; j++) out[t * 8 + j] = acc[j] * inv;
    }
}

// ---------------- host ----------------
extern "C" void kernel_launch(void* const* d_in, const int* in_sizes, int n_in,
                              void* d_out, int out_size)
{
    int ix, ish, ilen, iW1, ib1, iW2, ib2, iW3, ib3, iWo, ibo, iei, ibatch;
    if (n_in >= 13 && (long long)in_sizes[1] == 9LL * (long long)in_sizes[2]) {
        ix = 0; ish = 1; ilen = 2; iW1 = 3; ib1 = 4; iW2 = 5; ib2 = 6;
        iW3 = 7; ib3 = 8; iWo = 9; ibo = 10; iei = 11; ibatch = 12;
    } else {
        ix = 0; iei = 1; ish = 2; ilen = 3; ibatch = 4; iW1 = 5; ib1 = 6;
        iW2 = 7; ib2 = 8; iW3 = 9; ib3 = 10; iWo = 11; ibo = 12;
    }

    const float* x     = (const float*)d_in[ix];
    const float* esh   = (const float*)d_in[ish];
    const float* elen  = (const float*)d_in[ilen];
    const float* W1    = (const float*)d_in[iW1];
    const float* b1    = (const float*)d_in[ib1];
    const float* W2    = (const float*)d_in[iW2];
    const float* b2    = (const float*)d_in[ib2];
    const float* W3    = (const float*)d_in[iW3];
    const float* b3    = (const float*)d_in[ib3];
    const float* Wo    = (const float*)d_in[iWo];
    const float* bo    = (const float*)d_in[ibo];
    const int*   ei    = (const int*)d_in[iei];
    const int*   batch = (const int*)d_in[ibatch];

    int N = in_sizes[ix];
    int E = in_sizes[ilen];
    if (N > NMAX) N = NMAX;
    if (E > EMAX) E = EMAX;

    int nbE = (E + 255) / 256;
    int nbS = (N + SCAN_B - 1) / SCAN_B;
    int nbW = (N * 32 + 255) / 256;

    // Radial-weight tables (emb/cutoff inline; also zeroes g_cnt)
    k_tab_build_all<<<(TB_ROWS * 160 + 255) / 256, 256>>>(W1, b1, W2, b2, W3, b3);

    // CSR by dst + packed records
    k_hist<<<nbE, 256>>>(ei, E);            // also zeroes g_pool
    k_scan1<<<nbS, SCAN_B>>>(N);
    k_scan23<<<nbS, SCAN_B>>>(N);
    k_scatter<<<nbE, 256>>>(ei, elen, esh, x, E);

    // Layers (dst-major, fused norm-act)
    k_layer1<<<nbW, 256>>>(E, N);
    k_layer2<<<nbW, 256>>>(E, N);
    k_layer3<<<nbW, 256>>>(batch, E, N);
    k_head<<<1, 256>>>(Wo, bo, (float*)d_out);
}

// round 17
// speedup vs baseline: 1.1017x; 1.0454x over previous
#include <cuda_runtime.h>
#include <cuda_fp16.h>
#include <math.h>
#include <stdint.h>

#define NMAX  50000
#define EMAX  800000
#define NGR   128

#define TB_BINS  3072          // bins over [0, 1.5), step 1/2048
#define TB_ROWS  (TB_BINS + 1)
#define TB_SCALE 2048.0f
#define TB_DMAX  1.49951f

#define SCAN_B 256

typedef unsigned long long u2;   // packed f32x2 {ch p, ch p+16}

// ---------------- scratch (static device arrays: no allocations) ----------------
// node features: [node*64 + p*4 + comp] as half2 {val(ch p), val(ch p+16)}
__device__ __half2 g_actA[(size_t)NMAX * 64];
__device__ __half2 g_actB[(size_t)NMAX * 64];
__device__ float   g_pool[NGR * 32];

// CSR by dst + packed edge records (CSR order), 32B each:
// u0 = { srcn, bin|xs<<16, h2(sh0,sh1), h2(sh2,sh3) }
// u1 = { h2(sh4,sh5), h2(sh6,sh7), h2(sh8,0), 0 }
__device__ int      g_cnt[NMAX];
__device__ int      g_off[NMAX];
__device__ int      g_pos[NMAX];
__device__ unsigned g_erec[(size_t)EMAX * 8];
__device__ int      g_bsum[(NMAX + SCAN_B - 1) / SCAN_B + 1];

// radial-weight tables (cutoff folded in), channel-pair packed:
// tab1/3: [row*32 + p*2 + path]   (2 paths)
// tab2:   [row*128 + p*8 + path]  (6 paths, slots 6,7 padding)
__device__ __half2 g_tab1p[(size_t)TB_ROWS * 32];
__device__ __half2 g_tab2p[(size_t)TB_ROWS * 128];
__device__ __half2 g_tab3p[(size_t)TB_ROWS * 32];

// ---------------- f32x2 helpers ----------------
__device__ __forceinline__ u2 pk2(float lo, float hi) {
    u2 r; asm("mov.b64 %0, {%1,%2};" : "=l"(r) : "f"(lo), "f"(hi)); return r;
}
__device__ __forceinline__ u2 dup2f(float v) {
    u2 r; asm("mov.b64 %0, {%1,%1};" : "=l"(r) : "f"(v)); return r;
}
__device__ __forceinline__ void upk2(float& lo, float& hi, u2 v) {
    asm("mov.b64 {%0,%1}, %2;" : "=f"(lo), "=f"(hi) : "l"(v));
}
__device__ __forceinline__ u2 fma2(u2 a, u2 b, u2 c) {
    u2 d; asm("fma.rn.f32x2 %0, %1, %2, %3;" : "=l"(d) : "l"(a), "l"(b), "l"(c)); return d;
}
__device__ __forceinline__ u2 mul2(u2 a, u2 b) {
    u2 d; asm("mul.rn.f32x2 %0, %1, %2;" : "=l"(d) : "l"(a), "l"(b)); return d;
}
__device__ __forceinline__ u2 neg2(u2 a) { return a ^ 0x8000000080000000ULL; }
__device__ __forceinline__ u2 dupc(float v) {
    u2 b = (u2)__float_as_uint(v); return b | (b << 32);
}
__device__ __forceinline__ u2 h2u2(unsigned bits) {   // half2 -> packed f32x2
    float2 f = __half22float2(*reinterpret_cast<__half2*>(&bits));
    return pk2(f.x, f.y);
}
__device__ __forceinline__ float2 h2f(unsigned bits) {
    __half2 h = *reinterpret_cast<__half2*>(&bits);
    return __half22float2(h);
}

// ---------------- scalar helpers ----------------
__device__ __forceinline__ float sspf(float x) {
    return fmaxf(x, 0.f) + log1pf(__expf(-fabsf(x))) - 0.69314718055994530942f;
}
__device__ __forceinline__ float cutoff_w(float d) {
    float u = d * (1.0f / 1.5f);
    if (u >= 1.f) return 0.f;
    float u2v = u * u;
    float u6 = u2v * u2v * u2v;
    return 1.f + u6 * (-28.f + u * (48.f - 21.f * u));
}

// ---------------- table generation (emb/cutoff inline) + g_cnt zeroing ----------------
// per_row = 32(t1) + 96(t2 used) + 32(t3) = 160 slots
__global__ void k_tab_build_all(
    const float* __restrict__ W1, const float* __restrict__ b1,
    const float* __restrict__ W2, const float* __restrict__ b2,
    const float* __restrict__ W3, const float* __restrict__ b3)
{
    int t = blockIdx.x * blockDim.x + threadIdx.x;
    if (t < NMAX) g_cnt[t] = 0;                 // fold g_cnt zeroing in here
    if (t >= TB_ROWS * 160) return;
    int r = t / 160, rem = t - r * 160;

    float d = (float)r * (1.0f / TB_SCALE);
    float ew = cutoff_w(d);
    float emb[10];
    #pragma unroll
    for (int k = 0; k < 10; k++) {
        float mu = 0.7f + (float)k * 0.111111111111111111f;
        float dd = d - mu;
        emb[k] = __expf(-50.f * dd * dd);
    }

    const float* W; const float* b; __half2* out; int C; int oidx; int p; int path;
    if (rem < 32) {
        p = rem >> 1; path = rem & 1;
        W = W1; b = b1; C = 64; out = g_tab1p; oidx = r * 32 + rem;
    } else if (rem < 128) {
        int q = rem - 32; p = q / 6; path = q - p * 6;
        W = W2; b = b2; C = 192; out = g_tab2p; oidx = r * 128 + p * 8 + path;
    } else {
        int q = rem - 128; p = q >> 1; path = q & 1;
        W = W3; b = b3; C = 64; out = g_tab3p; oidx = r * 32 + q;
    }

    int clo = path * 32 + p;
    int chi = clo + 16;
    float vl = b[clo], vh = b[chi];
    #pragma unroll
    for (int k = 0; k < 10; k++) {
        vl = fmaf(emb[k], W[k * C + clo], vl);
        vh = fmaf(emb[k], W[k * C + chi], vh);
    }
    out[oidx] = __floats2half2_rn(vl * ew, vh * ew);
}

// ---------------- CSR build ----------------
__global__ void k_hist(const int* __restrict__ ei, int E)
{
    int e = blockIdx.x * blockDim.x + threadIdx.x;
    if (e < NGR * 32) g_pool[e] = 0.f;          // fold pool zeroing in here
    if (e < E) atomicAdd(&g_cnt[ei[E + e]], 1);
}

__global__ void k_scan1(int n)
{
    __shared__ int sh[SCAN_B];
    int gid = blockIdx.x * SCAN_B + threadIdx.x;
    int v = (gid < n) ? g_cnt[gid] : 0;
    sh[threadIdx.x] = v;
    __syncthreads();
    #pragma unroll
    for (int ofs = 1; ofs < SCAN_B; ofs <<= 1) {
        int t = (threadIdx.x >= ofs) ? sh[threadIdx.x - ofs] : 0;
        __syncthreads();
        sh[threadIdx.x] += t;
        __syncthreads();
    }
    if (gid < n) g_off[gid] = sh[threadIdx.x] - v;
    if (threadIdx.x == SCAN_B - 1) g_bsum[blockIdx.x] = sh[SCAN_B - 1];
}

__global__ void k_scan23(int n)
{
    __shared__ int warp_part[8];
    int nb = blockIdx.x;
    int acc = 0;
    for (int i = threadIdx.x; i < nb; i += SCAN_B) acc += g_bsum[i];
    #pragma unroll
    for (int o = 16; o > 0; o >>= 1) acc += __shfl_down_sync(0xffffffffu, acc, o);
    if ((threadIdx.x & 31) == 0) warp_part[threadIdx.x >> 5] = acc;
    __syncthreads();
    if (threadIdx.x == 0) {
        int s = 0;
        #pragma unroll
        for (int w = 0; w < 8; w++) s += warp_part[w];
        warp_part[0] = s;
    }
    __syncthreads();
    int blockOfs = warp_part[0];
    int gid = blockIdx.x * SCAN_B + threadIdx.x;
    if (gid < n) {
        int o = g_off[gid] + blockOfs;
        g_off[gid] = o;
        g_pos[gid] = o;
    }
}

__global__ void k_scatter(const int* __restrict__ ei, const float* __restrict__ elen,
                          const float* __restrict__ esh, const float* __restrict__ x, int E)
{
    int e = blockIdx.x * blockDim.x + threadIdx.x;
    if (e >= E) return;
    int d = ei[E + e];
    int p = atomicAdd(&g_pos[d], 1);
    int s = ei[e];
    float dd = elen[e];
    float tt = fminf(fmaxf(dd, 0.f), TB_DMAX) * TB_SCALE;
    unsigned bin = (unsigned)(int)(tt + 0.5f);
    const float* sh = esh + (size_t)e * 9;

    __half xsh = __float2half_rn(x[s]);
    unsigned w1 = bin | ((unsigned)__half_as_ushort(xsh) << 16);
    __half2 p01 = __floats2half2_rn(sh[0], sh[1]);
    __half2 p23 = __floats2half2_rn(sh[2], sh[3]);
    __half2 p45 = __floats2half2_rn(sh[4], sh[5]);
    __half2 p67 = __floats2half2_rn(sh[6], sh[7]);
    __half2 p8z = __floats2half2_rn(sh[8], 0.f);

    uint4 u0 = make_uint4((unsigned)s, w1,
                          *reinterpret_cast<unsigned*>(&p01),
                          *reinterpret_cast<unsigned*>(&p23));
    uint4 u1 = make_uint4(*reinterpret_cast<unsigned*>(&p45),
                          *reinterpret_cast<unsigned*>(&p67),
                          *reinterpret_cast<unsigned*>(&p8z), 0u);
    uint4* out = (uint4*)(g_erec + (size_t)p * 8);
    out[0] = u0; out[1] = u1;
}

// ---------------- feature fetch / write (channel-pair form) ----------------
__device__ __forceinline__ void gather2(const __half2* base, int node, int p,
                                        u2& x0, u2& xv0, u2& xv1, u2& xv2)
{
    uint4 raw = __ldg((const uint4*)(base + (size_t)node * 64 + p * 4));
    x0  = h2u2(raw.x);
    xv0 = h2u2(raw.y);
    xv1 = h2u2(raw.z);
    xv2 = h2u2(raw.w);
}

__device__ __forceinline__ void write_na2(__half2* base, int node, int p,
                                          u2 s, u2 v0, u2 v1, u2 v2)
{
    float sl, sh_, al, ah, bl, bh, cl, ch;
    upk2(sl, sh_, s);
    upk2(al, ah, v0);
    upk2(bl, bh, v1);
    upk2(cl, ch, v2);
    float nl = sqrtf(al * al + bl * bl + cl * cl + 1e-12f);
    float nh = sqrtf(ah * ah + bh * bh + ch * ch + 1e-12f);
    float scl = sspf(nl) / nl;
    float sch = sspf(nh) / nh;
    uint4 o;
    __half2 h0 = __floats2half2_rn(sspf(sl), sspf(sh_));
    __half2 h1 = __floats2half2_rn(al * scl, ah * sch);
    __half2 h2v = __floats2half2_rn(bl * scl, bh * sch);
    __half2 h3 = __floats2half2_rn(cl * scl, ch * sch);
    o.x = *reinterpret_cast<unsigned*>(&h0);
    o.y = *reinterpret_cast<unsigned*>(&h1);
    o.z = *reinterpret_cast<unsigned*>(&h2v);
    o.w = *reinterpret_cast<unsigned*>(&h3);
    *(uint4*)(base + (size_t)node * 64 + p * 4) = o;
}

// ---------------- layer 1 (2 nodes/warp, 2 channels/thread) ----------------
__global__ void __launch_bounds__(256) k_layer1(int E, int N)
{
    int warp = (blockIdx.x * blockDim.x + threadIdx.x) >> 5;
    int lane = threadIdx.x & 31;
    int node = warp * 2 + (lane >> 4);
    if (node >= N) return;
    int p = lane & 15;
    int beg = __ldg(&g_off[node]);
    int end = (node + 1 < N) ? __ldg(&g_off[node + 1]) : E;

    u2 a0 = 0, a1 = 0, a2 = 0, a3 = 0;
    #pragma unroll 2
    for (int i = beg; i < end; i++) {
        uint4 u0 = __ldg((const uint4*)(g_erec + (size_t)i * 8));
        int bin = (int)(u0.y & 0xFFFFu);
        float xs = __half2float(__ushort_as_half((unsigned short)(u0.y >> 16)));
        float2 s01 = h2f(u0.z);
        float2 s23 = h2f(u0.w);
        uint2 wv = __ldg((const uint2*)(g_tab1p + (size_t)bin * 32 + p * 2));
        u2 w0 = h2u2(wv.x), w1 = h2u2(wv.y);
        u2 xs2 = dup2f(xs);
        u2 xw0 = mul2(xs2, w0);
        u2 xw1 = mul2(xs2, w1);
        a0 = fma2(xw0, dup2f(s01.x), a0);
        a1 = fma2(xw1, dup2f(s01.y), a1);
        a2 = fma2(xw1, dup2f(s23.x), a2);
        a3 = fma2(xw1, dup2f(s23.y), a3);
    }
    write_na2(g_actA, node, p, a0, a1, a2, a3);
}

// ---------------- layer 2 (2 nodes/warp, 2 channels/thread, f32x2 math) ----------------
__global__ void __launch_bounds__(256) k_layer2(int E, int N)
{
    int warp = (blockIdx.x * blockDim.x + threadIdx.x) >> 5;
    int lane = threadIdx.x & 31;
    int node = warp * 2 + (lane >> 4);
    if (node >= N) return;
    int p = lane & 15;
    int beg = __ldg(&g_off[node]);
    int end = (node + 1 < N) ? __ldg(&g_off[node + 1]) : E;

    const u2 C_nRT3 = dupc(-0.57735026918962576451f);  // -1/sqrt(3)
    const u2 C_nRT2 = dupc(-0.70710678118654752440f);  // -1/sqrt(2)
    const u2 C_A    = dupc( 0.31622776601683793320f);  // 1/sqrt(10)
    const u2 C_2A   = dupc( 0.63245553203367586640f);  // 2/sqrt(10)
    const u2 C_B    = dupc( 0.54772255750516611346f);  // sqrt(3/10)

    u2 a0 = 0, a1 = 0, a2 = 0, a3 = 0;
    #pragma unroll 1
    for (int i = beg; i < end; i++) {
        const uint4* rp = (const uint4*)(g_erec + (size_t)i * 8);
        uint4 u0 = __ldg(rp);
        uint4 u1 = __ldg(rp + 1);
        int srcn = (int)u0.x;
        int bin  = (int)(u0.y & 0xFFFFu);

        u2 x0, xv0, xv1, xv2;
        gather2(g_actA, srcn, p, x0, xv0, xv1, xv2);

        const __half2* tb = g_tab2p + (size_t)bin * 128 + p * 8;
        uint4 wa = __ldg((const uint4*)tb);
        uint2 wb = __ldg((const uint2*)(tb + 4));
        u2 wp0 = h2u2(wa.x), wp1 = h2u2(wa.y), wp2 = h2u2(wa.z);
        u2 wp3 = h2u2(wa.w), wp4 = h2u2(wb.x), wp5 = h2u2(wb.y);

        float2 s01 = h2f(u0.z);
        float2 s23 = h2f(u0.w);
        float2 s45 = h2f(u1.x);
        float2 s67 = h2f(u1.y);
        float2 s8z = h2f(u1.z);
        u2 s0  = dup2f(s01.x);
        u2 sv0 = dup2f(s01.y), sv1 = dup2f(s23.x), sv2 = dup2f(s23.y);
        u2 t20 = dup2f(s45.x), t21 = dup2f(s45.y), t22 = dup2f(s67.x);
        u2 t23 = dup2f(s67.y), t24 = dup2f(s8z.x);

        u2 nxv0 = neg2(xv0), nxv1 = neg2(xv1), nxv2 = neg2(xv2);

        // paths (0,0,0) + (1,1,0)
        u2 dotv = fma2(xv2, sv2, fma2(xv1, sv1, mul2(xv0, sv0)));
        a0 = fma2(mul2(dotv, C_nRT3), wp3, fma2(mul2(s0, x0), wp0, a0));

        // path (1,1,1): -1/sqrt2 * cross
        u2 cr0 = fma2(nxv2, sv1, mul2(xv1, sv2));
        u2 cr1 = fma2(nxv0, sv2, mul2(xv2, sv0));
        u2 cr2 = fma2(nxv1, sv0, mul2(xv0, sv1));

        // path (1,2,1): real CG(1,2,1) contraction
        u2 axv0   = mul2(xv0, C_A);
        u2 bxv0   = mul2(xv0, C_B);
        u2 nbxv0  = neg2(bxv0);
        u2 nbxv1  = mul2(nxv1, C_B);
        u2 nbxv2  = mul2(nxv2, C_B);
        u2 n2axv1 = mul2(nxv1, C_2A);
        u2 axv2   = mul2(xv2, C_A);
        u2 t50 = fma2(nbxv2, t20, fma2(nbxv1, t21, fma2(bxv0, t24, mul2(axv0, t22))));
        u2 t51 = fma2(nbxv2, t23, fma2(n2axv1, t22, mul2(nbxv0, t21)));
        u2 t52 = fma2(nbxv2, t24, fma2(axv2, t22, fma2(nbxv1, t23, mul2(nbxv0, t20))));

        u2 x0w1 = mul2(x0, wp1);
        u2 s0w2 = mul2(s0, wp2);
        u2 wn4  = mul2(wp4, C_nRT2);
        a1 = fma2(t50, wp5, fma2(cr0, wn4, fma2(xv0, s0w2, fma2(sv0, x0w1, a1))));
        a2 = fma2(t51, wp5, fma2(cr1, wn4, fma2(xv1, s0w2, fma2(sv1, x0w1, a2))));
        a3 = fma2(t52, wp5, fma2(cr2, wn4, fma2(xv2, s0w2, fma2(sv2, x0w1, a3))));
    }
    write_na2(g_actB, node, p, a0, a1, a2, a3);
}

// ---------------- layer 3 (2 nodes/warp, 2 channels/thread) + silu + pool ----------------
__global__ void __launch_bounds__(256) k_layer3(const int* __restrict__ batch, int E, int N)
{
    int warp = (blockIdx.x * blockDim.x + threadIdx.x) >> 5;
    int lane = threadIdx.x & 31;
    int node = warp * 2 + (lane >> 4);
    if (node >= N) return;
    int p = lane & 15;
    int beg = __ldg(&g_off[node]);
    int end = (node + 1 < N) ? __ldg(&g_off[node + 1]) : E;

    const u2 C_nRT3 = dupc(-0.57735026918962576451f);
    u2 h = 0;
    #pragma unroll 2
    for (int i = beg; i < end; i++) {
        uint4 u0 = __ldg((const uint4*)(g_erec + (size_t)i * 8));
        int srcn = (int)u0.x;
        int bin  = (int)(u0.y & 0xFFFFu);

        u2 x0, xv0, xv1, xv2;
        gather2(g_actB, srcn, p, x0, xv0, xv1, xv2);

        uint2 wv = __ldg((const uint2*)(g_tab3p + (size_t)bin * 32 + p * 2));
        u2 w0 = h2u2(wv.x), w1 = h2u2(wv.y);

        float2 s01 = h2f(u0.z);
        float2 s23 = h2f(u0.w);
        u2 dotv = fma2(xv2, dup2f(s23.y), fma2(xv1, dup2f(s23.x), mul2(xv0, dup2f(s01.y))));
        h = fma2(mul2(dotv, C_nRT3), w1, fma2(mul2(x0, dup2f(s01.x)), w0, h));
    }
    float hl, hh;
    upk2(hl, hh, h);
    float yl = hl / (1.f + __expf(-hl));
    float yh = hh / (1.f + __expf(-hh));
    int b = __ldg(&batch[node]);
    atomicAdd(&g_pool[b * 32 + p], yl);
    atomicAdd(&g_pool[b * 32 + p + 16], yh);
}

// ---------------- head ----------------
__global__ void k_head(const float* __restrict__ Wo, const float* __restrict__ bo,
                       float* __restrict__ out)
{
    __shared__ float Ws[32 * 8];
    __shared__ float bs[8];
    int t = threadIdx.x;
    if (t < 256) Ws[t] = Wo[t];
    if (t < 8)   bs[t] = bo[t];
    __syncthreads();
    if (t < NGR) {
        float acc[8];
        #pragma unroll
        for (int j = 0; j < 8; j++) acc[j] = bs[j];
        #pragma unroll
        for (int k = 0; k < 32; k++) {
            float gv = g_pool[t * 32 + k];
            #pragma unroll
            for (int j = 0; j < 8; j++) acc[j] = fmaf(gv, Ws[k * 8 + j], acc[j]);
        }
        float mx = acc[0];
        #pragma unroll
        for (int j = 1; j < 8; j++) mx = fmaxf(mx, acc[j]);
        float sm = 0.f;
        #pragma unroll
        for (int j = 0; j < 8; j++) { acc[j] = __expf(acc[j] - mx); sm += acc[j]; }
        float inv = 1.f / sm;
        #pragma unroll
        for (int j = 0; j < 8; j++) out[t * 8 + j] = acc[j] * inv;
    }
}

// ---------------- host ----------------
extern "C" void kernel_launch(void* const* d_in, const int* in_sizes, int n_in,
                              void* d_out, int out_size)
{
    int ix, ish, ilen, iW1, ib1, iW2, ib2, iW3, ib3, iWo, ibo, iei, ibatch;
    if (n_in >= 13 && (long long)in_sizes[1] == 9LL * (long long)in_sizes[2]) {
        ix = 0; ish = 1; ilen = 2; iW1 = 3; ib1 = 4; iW2 = 5; ib2 = 6;
        iW3 = 7; ib3 = 8; iWo = 9; ibo = 10; iei = 11; ibatch = 12;
    } else {
        ix = 0; iei = 1; ish = 2; ilen = 3; ibatch = 4; iW1 = 5; ib1 = 6;
        iW2 = 7; ib2 = 8; iW3 = 9; ib3 = 10; iWo = 11; ibo = 12;
    }

    const float* x     = (const float*)d_in[ix];
    const float* esh   = (const float*)d_in[ish];
    const float* elen  = (const float*)d_in[ilen];
    const float* W1    = (const float*)d_in[iW1];
    const float* b1    = (const float*)d_in[ib1];
    const float* W2    = (const float*)d_in[iW2];
    const float* b2    = (const float*)d_in[ib2];
    const float* W3    = (const float*)d_in[iW3];
    const float* b3    = (const float*)d_in[ib3];
    const float* Wo    = (const float*)d_in[iWo];
    const float* bo    = (const float*)d_in[ibo];
    const int*   ei    = (const int*)d_in[iei];
    const int*   batch = (const int*)d_in[ibatch];

    int N = in_sizes[ix];
    int E = in_sizes[ilen];
    if (N > NMAX) N = NMAX;
    if (E > EMAX) E = EMAX;

    int nbE  = (E + 255) / 256;
    int nbS  = (N + SCAN_B - 1) / SCAN_B;
    int nwp  = (N + 1) / 2;                       // 2 nodes per warp
    int nbW  = (nwp * 32 + 255) / 256;

    // Radial-weight tables (emb/cutoff inline; also zeroes g_cnt)
    k_tab_build_all<<<(TB_ROWS * 160 + 255) / 256, 256>>>(W1, b1, W2, b2, W3, b3);

    // CSR by dst + packed records
    k_hist<<<nbE, 256>>>(ei, E);            // also zeroes g_pool
    k_scan1<<<nbS, SCAN_B>>>(N);
    k_scan23<<<nbS, SCAN_B>>>(N);
    k_scatter<<<nbE, 256>>>(ei, elen, esh, x, E);

    // Layers (dst-major, channel-pair f32x2, fused norm-act)
    k_layer1<<<nbW, 256>>>(E, N);
    k_layer2<<<nbW, 256>>>(E, N);
    k_layer3<<<nbW, 256>>>(batch, E, N);
    k_head<<<1, 256>>>(Wo, bo, (float*)d_out);
}